// round 13
// baseline (speedup 1.0000x reference)
#include <cuda_runtime.h>
#include <math.h>

// ---------------- problem constants (fixed by setup_inputs) ----------------
#define HDIM 28
#define NTOK 21952          // 28^3
#define C_ 256
#define NR 343              // 7^3 (SR-conv output tokens)
#define H2_ 4               // heads per branch
#define SCALE_F 0.17677669529663687f   // 32^-0.5
#define KSR 16384           // 256*4*4*4 im2col K
#define KZ 64               // split-K chunks for SR conv: one per kernel position
#define NP 768              // packed projection width: q1|q2|kv2|y

typedef unsigned long long u64;

// ---- packed f32x2 helpers (sm_103a FFMA2 path; ptxas never auto-generates) ----
__device__ __forceinline__ u64 pk2(float lo, float hi) {
    u64 r; asm("mov.b64 %0,{%1,%2};" : "=l"(r) : "f"(lo), "f"(hi)); return r;
}
__device__ __forceinline__ u64 bc2(float v) { return pk2(v, v); }
__device__ __forceinline__ u64 f2fma(u64 a, u64 b, u64 c) {
    u64 d; asm("fma.rn.f32x2 %0,%1,%2,%3;" : "=l"(d) : "l"(a), "l"(b), "l"(c)); return d;
}
__device__ __forceinline__ void up2(u64 v, float& lo, float& hi) {
    asm("mov.b64 {%0,%1},%2;" : "=f"(lo), "=f"(hi) : "l"(v));
}

// ---------------- scratch (device globals; no allocation) ----------------
__device__ float g_p   [NTOK*NP];     // packed: [0,128)=q1 [128,256)=q2 [256,512)=kv2 [512,768)=y
__device__ float g_lepe[NTOK*C_];
__device__ float g_x1p [KZ*NR*C_];    // split-K partials (22.5 MB)
__device__ float g_x1  [NR*C_];
__device__ float g_kv1 [NR*C_];
__device__ float g_o   [NTOK*C_];
__device__ float g_wp  [NP*C_];       // packed projection weights
__device__ float g_bp  [NP];          // packed bias
__device__ float g_wsr [C_*KSR];      // sr_w transposed: [cout][kpos][cin]

// ---------------- weight packing (q1|q2|kv2|lepe) ----------------
__global__ void pack_w(const float* __restrict__ q1w, const float* __restrict__ q2w,
                       const float* __restrict__ kv2w, const float* __restrict__ lepew,
                       const float* __restrict__ lepeb,
                       float* __restrict__ wp, float* __restrict__ bp) {
    int i = blockIdx.x * 256 + threadIdx.x;
    if (i < NP * C_) {
        int r = i >> 8, c = i & 255;
        float v;
        if (r < 128)      v = q1w[r * C_ + c];
        else if (r < 256) v = q2w[(r - 128) * C_ + c];
        else if (r < 512) v = kv2w[(r - 256) * C_ + c];
        else              v = lepew[(r - 512) * C_ + c];
        wp[i] = v;
    }
    if (i < NP) bp[i] = (i >= 512) ? lepeb[i - 512] : 0.f;
}

// -------- sr weight transpose: w[cout][cin][kpos] -> wsr[cout][kpos][cin] --------
__global__ void pack_wsr(const float* __restrict__ w, float* __restrict__ wsr) {
    __shared__ float t[32][257];
    const int cout = blockIdx.x;          // 256 blocks
    const int tid = threadIdx.x;          // 256 threads = cin
    const float* wr = w + (size_t)cout * KSR + (size_t)tid * 64;
    float* wo = wsr + (size_t)cout * KSR;
#pragma unroll
    for (int half = 0; half < 2; half++) {
#pragma unroll
        for (int j4 = 0; j4 < 8; j4++) {
            float4 v = *(const float4*)(wr + half * 32 + j4 * 4);
            t[j4*4+0][tid] = v.x; t[j4*4+1][tid] = v.y;
            t[j4*4+2][tid] = v.z; t[j4*4+3][tid] = v.w;
        }
        __syncthreads();
#pragma unroll
        for (int j = 0; j < 32; j++)
            wo[(size_t)(half * 32 + j) * C_ + tid] = t[j][tid];
        __syncthreads();
    }
}

// ------------- 128x128x16 fp32 GEMM, FFMA2 inner loop -------------
// out[M,Nc] = (A+A2)[M,K] @ W[Nc,K]^T + bias ; Nc multiple of 128, M guarded.
__global__ void __launch_bounds__(256, 2)
gemm128(const float* __restrict__ A, const float* __restrict__ A2,
        const float* __restrict__ W, const float* __restrict__ bias,
        float* __restrict__ out, int M, int K, int Nc) {
    __shared__ u64   As2[16][128];   // duplicated lanes (a,a) : 16 KB
    __shared__ float Ws [16][128];   // 8 KB
    const int tid = threadIdx.x;
    const int tx = tid & 15, ty = tid >> 4;
    const int bm = blockIdx.y << 7, bn = blockIdx.x << 7;

    const int lr = tid >> 1;          // 0..127 tile row for loads
    const int lc = (tid & 1) << 3;    // 0 or 8

    const int am = bm + lr;
    const bool aval = am < M;
    const float* Ap  = A + (size_t)am * K + lc;
    const float* A2p = A2 ? A2 + (size_t)am * K + lc : nullptr;
    const float* Wp  = W + (size_t)(bn + lr) * K + lc;

    float4 a0 = make_float4(0.f,0.f,0.f,0.f), a1 = a0, w0, w1;
    if (aval) {
        a0 = *(const float4*)(Ap);
        a1 = *(const float4*)(Ap + 4);
        if (A2p) {
            float4 b = *(const float4*)(A2p);
            a0.x += b.x; a0.y += b.y; a0.z += b.z; a0.w += b.w;
            b = *(const float4*)(A2p + 4);
            a1.x += b.x; a1.y += b.y; a1.z += b.z; a1.w += b.w;
        }
    }
    w0 = *(const float4*)(Wp);
    w1 = *(const float4*)(Wp + 4);

    u64 acc[8][4];
#pragma unroll
    for (int i = 0; i < 8; i++)
#pragma unroll
        for (int j = 0; j < 4; j++) acc[i][j] = 0ULL;

    for (int k0 = 0; k0 < K; k0 += 16) {
        As2[lc+0][lr]=bc2(a0.x); As2[lc+1][lr]=bc2(a0.y);
        As2[lc+2][lr]=bc2(a0.z); As2[lc+3][lr]=bc2(a0.w);
        As2[lc+4][lr]=bc2(a1.x); As2[lc+5][lr]=bc2(a1.y);
        As2[lc+6][lr]=bc2(a1.z); As2[lc+7][lr]=bc2(a1.w);
        Ws[lc+0][lr]=w0.x; Ws[lc+1][lr]=w0.y; Ws[lc+2][lr]=w0.z; Ws[lc+3][lr]=w0.w;
        Ws[lc+4][lr]=w1.x; Ws[lc+5][lr]=w1.y; Ws[lc+6][lr]=w1.z; Ws[lc+7][lr]=w1.w;
        __syncthreads();

        const int kn = k0 + 16;
        if (kn < K) {
            a0 = make_float4(0.f,0.f,0.f,0.f); a1 = a0;
            if (aval) {
                a0 = *(const float4*)(Ap + kn);
                a1 = *(const float4*)(Ap + kn + 4);
                if (A2p) {
                    float4 b = *(const float4*)(A2p + kn);
                    a0.x += b.x; a0.y += b.y; a0.z += b.z; a0.w += b.w;
                    b = *(const float4*)(A2p + kn + 4);
                    a1.x += b.x; a1.y += b.y; a1.z += b.z; a1.w += b.w;
                }
            }
            w0 = *(const float4*)(Wp + kn);
            w1 = *(const float4*)(Wp + kn + 4);
        }

#pragma unroll
        for (int k = 0; k < 16; k++) {
            const u64* ar = &As2[k][ty << 3];
            ulonglong2 av01 = *(const ulonglong2*)(ar);
            ulonglong2 av23 = *(const ulonglong2*)(ar + 2);
            ulonglong2 av45 = *(const ulonglong2*)(ar + 4);
            ulonglong2 av67 = *(const ulonglong2*)(ar + 6);
            const u64* wr = (const u64*)&Ws[k][tx << 3];
            ulonglong2 wv01 = *(const ulonglong2*)(wr);
            ulonglong2 wv23 = *(const ulonglong2*)(wr + 2);
            u64 av[8] = {av01.x, av01.y, av23.x, av23.y, av45.x, av45.y, av67.x, av67.y};
            u64 wv[4] = {wv01.x, wv01.y, wv23.x, wv23.y};
#pragma unroll
            for (int i = 0; i < 8; i++)
#pragma unroll
                for (int j = 0; j < 4; j++) acc[i][j] = f2fma(av[i], wv[j], acc[i][j]);
        }
        __syncthreads();
    }

    const int c0 = bn + (tx << 3);
    float b0[8];
#pragma unroll
    for (int j = 0; j < 8; j++) b0[j] = bias ? bias[c0 + j] : 0.f;
#pragma unroll
    for (int i = 0; i < 8; i++) {
        int r = bm + (ty << 3) + i;
        if (r < M) {
            float v[8];
#pragma unroll
            for (int j = 0; j < 4; j++) up2(acc[i][j], v[2*j], v[2*j+1]);
            float* op = out + (size_t)r * Nc + c0;
            *(float4*)op       = make_float4(v[0]+b0[0], v[1]+b0[1], v[2]+b0[2], v[3]+b0[3]);
            *(float4*)(op + 4) = make_float4(v[4]+b0[4], v[5]+b0[5], v[6]+b0[6], v[7]+b0[7]);
        }
    }
}

// ---- SR conv split-K GEMM (FFMA2): one block-z per kernel position ----
__global__ void __launch_bounds__(256, 2)
srconv_gemm(const float* __restrict__ x, const float* __restrict__ wsr,
            float* __restrict__ part) {
    __shared__ u64   As2[16][128];
    __shared__ float Ws [16][128];
    const int tid = threadIdx.x;
    const int tx = tid & 15, ty = tid >> 4;
    const int bn = blockIdx.x << 7;   // cout tile
    const int bm = blockIdx.y << 7;   // nr tile
    const int kz = blockIdx.z;        // kernel position 0..63

    const int kh = kz >> 4, kw = (kz >> 2) & 3, kd = kz & 3;

    const int lr = tid >> 1;
    const int lc = (tid & 1) << 3;

    const int nr = bm + lr;
    const bool aval = nr < NR;
    int tok = 0;
    if (aval) {
        int oh = nr / 49; int r = nr % 49; int ow = r / 7; int od = r % 7;
        tok = ((4 * oh + kh) * HDIM + 4 * ow + kw) * HDIM + 4 * od + kd;
    }
    const float* Ap = x + (size_t)tok * C_ + lc;
    const float* Wp = wsr + (size_t)(bn + lr) * KSR + (size_t)kz * C_ + lc;

    float4 a0 = make_float4(0.f,0.f,0.f,0.f), a1 = a0, w0, w1;
    if (aval) { a0 = *(const float4*)(Ap); a1 = *(const float4*)(Ap + 4); }
    w0 = *(const float4*)(Wp);
    w1 = *(const float4*)(Wp + 4);

    u64 acc[8][4];
#pragma unroll
    for (int i = 0; i < 8; i++)
#pragma unroll
        for (int j = 0; j < 4; j++) acc[i][j] = 0ULL;

    for (int k0 = 0; k0 < C_; k0 += 16) {
        As2[lc+0][lr]=bc2(a0.x); As2[lc+1][lr]=bc2(a0.y);
        As2[lc+2][lr]=bc2(a0.z); As2[lc+3][lr]=bc2(a0.w);
        As2[lc+4][lr]=bc2(a1.x); As2[lc+5][lr]=bc2(a1.y);
        As2[lc+6][lr]=bc2(a1.z); As2[lc+7][lr]=bc2(a1.w);
        Ws[lc+0][lr]=w0.x; Ws[lc+1][lr]=w0.y; Ws[lc+2][lr]=w0.z; Ws[lc+3][lr]=w0.w;
        Ws[lc+4][lr]=w1.x; Ws[lc+5][lr]=w1.y; Ws[lc+6][lr]=w1.z; Ws[lc+7][lr]=w1.w;
        __syncthreads();

        const int kn = k0 + 16;
        if (kn < C_) {
            a0 = make_float4(0.f,0.f,0.f,0.f); a1 = a0;
            if (aval) { a0 = *(const float4*)(Ap + kn); a1 = *(const float4*)(Ap + kn + 4); }
            w0 = *(const float4*)(Wp + kn);
            w1 = *(const float4*)(Wp + kn + 4);
        }

#pragma unroll
        for (int k = 0; k < 16; k++) {
            const u64* ar = &As2[k][ty << 3];
            ulonglong2 av01 = *(const ulonglong2*)(ar);
            ulonglong2 av23 = *(const ulonglong2*)(ar + 2);
            ulonglong2 av45 = *(const ulonglong2*)(ar + 4);
            ulonglong2 av67 = *(const ulonglong2*)(ar + 6);
            const u64* wr = (const u64*)&Ws[k][tx << 3];
            ulonglong2 wv01 = *(const ulonglong2*)(wr);
            ulonglong2 wv23 = *(const ulonglong2*)(wr + 2);
            u64 av[8] = {av01.x, av01.y, av23.x, av23.y, av45.x, av45.y, av67.x, av67.y};
            u64 wv[4] = {wv01.x, wv01.y, wv23.x, wv23.y};
#pragma unroll
            for (int i = 0; i < 8; i++)
#pragma unroll
                for (int j = 0; j < 4; j++) acc[i][j] = f2fma(av[i], wv[j], acc[i][j]);
        }
        __syncthreads();
    }

    const int c0 = bn + (tx << 3);
    float* pz = part + (size_t)kz * (NR * C_);
#pragma unroll
    for (int i = 0; i < 8; i++) {
        int r = bm + (ty << 3) + i;
        if (r < NR) {
            float v[8];
#pragma unroll
            for (int j = 0; j < 4; j++) up2(acc[i][j], v[2*j], v[2*j+1]);
            float* op = pz + (size_t)r * C_ + c0;
            *(float4*)op       = make_float4(v[0], v[1], v[2], v[3]);
            *(float4*)(op + 4) = make_float4(v[4], v[5], v[6], v[7]);
        }
    }
}

__global__ void sr_reduce(float* __restrict__ x1, const float* __restrict__ part) {
    int i4 = blockIdx.x * 256 + threadIdx.x;     // float4 index
    const int n4 = NR * C_ / 4;                  // 21952
    if (i4 < n4) {
        float4 s = make_float4(0.f, 0.f, 0.f, 0.f);
#pragma unroll
        for (int z = 0; z < KZ; z++) {
            float4 v = ((const float4*)part)[(size_t)z * n4 + i4];
            s.x += v.x; s.y += v.y; s.z += v.z; s.w += v.w;
        }
        ((float4*)x1)[i4] = s;
    }
}

// ------- depthwise 3x3x3 SAME conv, channel pairs via FFMA2; input packed y -------
__global__ void dwconv3(const float* __restrict__ p, const float* __restrict__ w,
                        const float* __restrict__ b, float* __restrict__ out) {
    const int n = blockIdx.x;
    const int c2 = threadIdx.x;          // 0..127 -> channels 2c2, 2c2+1
    const int c = c2 * 2;
    const int d  = n % HDIM;
    const int wv = (n / HDIM) % HDIM;
    const int h  = n / (HDIM * HDIM);

    u64 wreg[27];
#pragma unroll
    for (int j = 0; j < 27; j++) wreg[j] = pk2(w[c * 27 + j], w[(c + 1) * 27 + j]);

    u64 acc = pk2(b[c], b[c + 1]);
#pragma unroll
    for (int kh = 0; kh < 3; kh++) {
        int hh = h + kh - 1;
        if (hh < 0 || hh >= HDIM) continue;
#pragma unroll
        for (int kw = 0; kw < 3; kw++) {
            int ww = wv + kw - 1;
            if (ww < 0 || ww >= HDIM) continue;
#pragma unroll
            for (int kd = 0; kd < 3; kd++) {
                int dd = d + kd - 1;
                if (dd < 0 || dd >= HDIM) continue;
                u64 in = *(const u64*)(p + (size_t)((hh * HDIM + ww) * HDIM + dd) * NP + 512 + c);
                acc = f2fma(wreg[kh * 9 + kw * 3 + kd], in, acc);
            }
        }
    }
    *(u64*)(out + (size_t)n * C_ + c) = acc;
}

// ---------------- layernorm (+sr bias) + exact GELU, in place ----------------
__global__ void ln_gelu(float* __restrict__ x1, const float* __restrict__ srb,
                        const float* __restrict__ g, const float* __restrict__ b) {
    __shared__ float red[256];
    const int r = blockIdx.x, c = threadIdx.x;
    float v = x1[(size_t)r * C_ + c] + srb[c];

    red[c] = v; __syncthreads();
    for (int s = 128; s > 0; s >>= 1) { if (c < s) red[c] += red[c + s]; __syncthreads(); }
    float mu = red[0] * (1.f / 256.f);
    __syncthreads();

    float dv = v - mu;
    red[c] = dv * dv; __syncthreads();
    for (int s = 128; s > 0; s >>= 1) { if (c < s) red[c] += red[c + s]; __syncthreads(); }
    float var = red[0] * (1.f / 256.f);

    float xn = dv * rsqrtf(var + 1e-5f) * g[c] + b[c];
    float out = 0.5f * xn * (1.f + erff(xn * 0.70710678118654752f));
    x1[(size_t)r * C_ + c] = out;
}

// ---------------- branch 1: global attention vs 343 reduced tokens (FFMA2) --------
#define CH1 176
__global__ void attn_global(const float* __restrict__ p, const float* __restrict__ kv1,
                            float* __restrict__ o) {
    __shared__ float4 sk[CH1][8];
    __shared__ float4 sv[CH1][8];
    const int h = blockIdx.y;
    const int n = blockIdx.x * 256 + threadIdx.x;
    const bool valid = n < NTOK;

    u64 q2[16];
    if (valid) {
        const float4* qp = (const float4*)(p + (size_t)n * NP + h * 32);
#pragma unroll
        for (int i = 0; i < 8; i++) {
            float4 t = qp[i];
            q2[2*i]   = pk2(t.x * SCALE_F, t.y * SCALE_F);
            q2[2*i+1] = pk2(t.z * SCALE_F, t.w * SCALE_F);
        }
    }

    float l = 0.f;
    u64 acc[16];
#pragma unroll
    for (int i = 0; i < 16; i++) acc[i] = 0ULL;

    for (int c0 = 0; c0 < NR; c0 += CH1) {
        const int cn = min(CH1, NR - c0);
        for (int idx = threadIdx.x; idx < cn * 8; idx += 256) {
            int m = idx >> 3, dq = idx & 7;
            sk[m][dq] = *(const float4*)(kv1 + (size_t)(c0 + m) * C_ + h * 32 + dq * 4);
            sv[m][dq] = *(const float4*)(kv1 + (size_t)(c0 + m) * C_ + 128 + h * 32 + dq * 4);
        }
        __syncthreads();
        if (valid) {
            for (int m = 0; m < cn; m++) {
                const u64* kk = (const u64*)&sk[m][0];
                u64 s2 = 0ULL;
#pragma unroll
                for (int i = 0; i < 16; i++) s2 = f2fma(q2[i], kk[i], s2);
                float slo, shi; up2(s2, slo, shi);
                float pw = __expf(slo + shi);
                l += pw;
                u64 pw2 = bc2(pw);
                const u64* vv = (const u64*)&sv[m][0];
#pragma unroll
                for (int i = 0; i < 16; i++) acc[i] = f2fma(pw2, vv[i], acc[i]);
            }
        }
        __syncthreads();
    }

    if (valid) {
        float inv = 1.f / l;
        float4* op = (float4*)(o + (size_t)n * C_ + h * 32);
#pragma unroll
        for (int i = 0; i < 8; i++) {
            float v0, v1, v2, v3;
            up2(acc[2*i], v0, v1); up2(acc[2*i+1], v2, v3);
            op[i] = make_float4(v0*inv, v1*inv, v2*inv, v3*inv);
        }
    }
}

// ---------------- branch 2: 7x7x7 windowed attention (packed q/kv, FFMA2) ---------
__global__ void attn_window(const float* __restrict__ p, float* __restrict__ o) {
    __shared__ float4 sk[CH1][8];
    __shared__ float4 sv[CH1][8];
    const int h = blockIdx.y;
    const int w = blockIdx.x;                 // 0..63
    const int wh = w >> 4, ww = (w >> 2) & 3, wd = w & 3;
    const int t = threadIdx.x;
    const bool valid = t < NR;

    int n = 0;
    if (valid) {
        int ih = t / 49, r = t % 49, iw = r / 7, id = r % 7;
        n = ((wh * 7 + ih) * HDIM + ww * 7 + iw) * HDIM + wd * 7 + id;
    }

    u64 q2[16];
    if (valid) {
        const float4* qp = (const float4*)(p + (size_t)n * NP + 128 + h * 32);
#pragma unroll
        for (int i = 0; i < 8; i++) {
            float4 tt = qp[i];
            q2[2*i]   = pk2(tt.x * SCALE_F, tt.y * SCALE_F);
            q2[2*i+1] = pk2(tt.z * SCALE_F, tt.w * SCALE_F);
        }
    }

    float l = 0.f;
    u64 acc[16];
#pragma unroll
    for (int i = 0; i < 16; i++) acc[i] = 0ULL;

    for (int c0 = 0; c0 < NR; c0 += CH1) {
        const int cn = min(CH1, NR - c0);
        for (int idx = t; idx < cn * 8; idx += 352) {
            int m = idx >> 3, dq = idx & 7;
            int tm = c0 + m;
            int ih = tm / 49, r = tm % 49, iw = r / 7, id = r % 7;
            int nm = ((wh * 7 + ih) * HDIM + ww * 7 + iw) * HDIM + wd * 7 + id;
            sk[m][dq] = *(const float4*)(p + (size_t)nm * NP + 256 + h * 32 + dq * 4);
            sv[m][dq] = *(const float4*)(p + (size_t)nm * NP + 384 + h * 32 + dq * 4);
        }
        __syncthreads();
        if (valid) {
            for (int m = 0; m < cn; m++) {
                const u64* kk = (const u64*)&sk[m][0];
                u64 s2 = 0ULL;
#pragma unroll
                for (int i = 0; i < 16; i++) s2 = f2fma(q2[i], kk[i], s2);
                float slo, shi; up2(s2, slo, shi);
                float pw = __expf(slo + shi);
                l += pw;
                u64 pw2 = bc2(pw);
                const u64* vv = (const u64*)&sv[m][0];
#pragma unroll
                for (int i = 0; i < 16; i++) acc[i] = f2fma(pw2, vv[i], acc[i]);
            }
        }
        __syncthreads();
    }

    if (valid) {
        float inv = 1.f / l;
        float4* op = (float4*)(o + (size_t)n * C_ + 128 + h * 32);
#pragma unroll
        for (int i = 0; i < 8; i++) {
            float v0, v1, v2, v3;
            up2(acc[2*i], v0, v1); up2(acc[2*i+1], v2, v3);
            op[i] = make_float4(v0*inv, v1*inv, v2*inv, v3*inv);
        }
    }
}

// ---------------- launch ----------------
extern "C" void kernel_launch(void* const* d_in, const int* in_sizes, int n_in,
                              void* d_out, int out_size) {
    const float* x       = (const float*)d_in[0];
    const float* lepe_w  = (const float*)d_in[4];
    const float* lepe_b  = (const float*)d_in[5];
    const float* lepe_cw = (const float*)d_in[6];
    const float* lepe_cb = (const float*)d_in[7];
    const float* sr_w    = (const float*)d_in[8];
    const float* sr_b    = (const float*)d_in[9];
    const float* norm_g  = (const float*)d_in[10];
    const float* norm_b  = (const float*)d_in[11];
    const float* q1_w    = (const float*)d_in[12];
    const float* kv1_w   = (const float*)d_in[13];
    const float* q2_w    = (const float*)d_in[14];
    const float* kv2_w   = (const float*)d_in[15];
    const float* proj_w  = (const float*)d_in[16];
    const float* proj_b  = (const float*)d_in[17];
    float* out = (float*)d_out;

    float *p, *lepe, *x1p, *x1, *kv1, *o, *wp, *bp, *wsr;
    cudaGetSymbolAddress((void**)&p,    g_p);
    cudaGetSymbolAddress((void**)&lepe, g_lepe);
    cudaGetSymbolAddress((void**)&x1p,  g_x1p);
    cudaGetSymbolAddress((void**)&x1,   g_x1);
    cudaGetSymbolAddress((void**)&kv1,  g_kv1);
    cudaGetSymbolAddress((void**)&o,    g_o);
    cudaGetSymbolAddress((void**)&wp,   g_wp);
    cudaGetSymbolAddress((void**)&bp,   g_bp);
    cudaGetSymbolAddress((void**)&wsr,  g_wsr);

    const int MT = (NTOK + 127) / 128;   // 172 row tiles

    // Pack projection weights, then one fused GEMM: [q1|q2|kv2|y] = x @ Wp^T + bp
    pack_w<<<(NP * C_ + 255) / 256, 256>>>(q1_w, q2_w, kv2_w, lepe_w, lepe_b, wp, bp);
    gemm128<<<dim3(NP / 128, MT), 256>>>(x, nullptr, wp, bp, p, NTOK, C_, NP);

    // LePE depthwise conv from packed y (channel pairs)
    dwconv3<<<NTOK, 128>>>(p, lepe_cw, lepe_cb, lepe);

    // SR conv: transpose weights, 64-way split-K contiguous GEMM, reduce, LN+GELU, kv1
    pack_wsr<<<C_, 256>>>(sr_w, wsr);
    srconv_gemm<<<dim3(C_ / 128, (NR + 127) / 128, KZ), 256>>>(x, wsr, x1p);
    sr_reduce<<<(NR * C_ / 4 + 255) / 256, 256>>>(x1, x1p);
    ln_gelu<<<NR, C_>>>(x1, sr_b, norm_g, norm_b);
    gemm128<<<dim3(C_ / 128, (NR + 127) / 128), 256>>>(x1, nullptr, kv1_w, nullptr, kv1, NR, C_, C_);

    // Attention branches -> g_o (cols 0..127 branch1, 128..255 branch2)
    attn_global<<<dim3((NTOK + 255) / 256, H2_), 256>>>(p, kv1, o);
    attn_window<<<dim3(64, H2_), 352>>>(p, o);

    // Final projection with fused (+lepe)
    gemm128<<<dim3(C_ / 128, MT), 256>>>(o, lepe, proj_w, proj_b, out, NTOK, C_, C_);
}

// round 14
// speedup vs baseline: 1.3664x; 1.3664x over previous
#include <cuda_runtime.h>
#include <math.h>

// ---------------- problem constants (fixed by setup_inputs) ----------------
#define HDIM 28
#define NTOK 21952          // 28^3
#define C_ 256
#define NR 343              // 7^3 (SR-conv output tokens)
#define H2_ 4               // heads per branch
#define SCALE_F 0.17677669529663687f   // 32^-0.5
#define KSR 16384           // 256*4*4*4 im2col K
#define KZ 64               // split-K chunks for SR conv: one per kernel position
#define NP 768              // packed projection width: q1|q2|kv2|y
#define SPAD 20             // smem row stride (words) for tf32 tiles: conflict-free

// ---------------- scratch (device globals; no allocation) ----------------
__device__ float g_p   [NTOK*NP];     // packed: [0,128)=q1 [128,256)=q2 [256,512)=kv2 [512,768)=y
__device__ float g_lepe[NTOK*C_];
__device__ float g_x1p [KZ*NR*C_];    // split-K partials (22.5 MB)
__device__ float g_x1  [NR*C_];
__device__ float g_kv1 [NR*C_];
__device__ float g_o   [NTOK*C_];
__device__ float g_wp  [NP*C_];       // packed projection weights
__device__ float g_bp  [NP];          // packed bias
__device__ float g_wsr [C_*KSR];      // sr_w transposed: [cout][kpos][cin]

// ---------------- tf32 mma helpers ----------------
__device__ __forceinline__ unsigned f2tf(float f) {
    unsigned u; asm("cvt.rna.tf32.f32 %0,%1;" : "=r"(u) : "f"(f)); return u;
}
__device__ __forceinline__ void mma8(float* c, unsigned a0, unsigned a1, unsigned a2,
                                     unsigned a3, unsigned b0, unsigned b1) {
    asm("mma.sync.aligned.m16n8k8.row.col.f32.tf32.tf32.f32 "
        "{%0,%1,%2,%3},{%4,%5,%6,%7},{%8,%9},{%0,%1,%2,%3};"
        : "+f"(c[0]), "+f"(c[1]), "+f"(c[2]), "+f"(c[3])
        : "r"(a0), "r"(a1), "r"(a2), "r"(a3), "r"(b0), "r"(b1));
}

// ---------------- weight packing (q1|q2|kv2|lepe) ----------------
__global__ void pack_w(const float* __restrict__ q1w, const float* __restrict__ q2w,
                       const float* __restrict__ kv2w, const float* __restrict__ lepew,
                       const float* __restrict__ lepeb,
                       float* __restrict__ wp, float* __restrict__ bp) {
    int i = blockIdx.x * 256 + threadIdx.x;
    if (i < NP * C_) {
        int r = i >> 8, c = i & 255;
        float v;
        if (r < 128)      v = q1w[r * C_ + c];
        else if (r < 256) v = q2w[(r - 128) * C_ + c];
        else if (r < 512) v = kv2w[(r - 256) * C_ + c];
        else              v = lepew[(r - 512) * C_ + c];
        wp[i] = v;
    }
    if (i < NP) bp[i] = (i >= 512) ? lepeb[i - 512] : 0.f;
}

// -------- sr weight transpose: w[cout][cin][kpos] -> wsr[cout][kpos][cin] --------
__global__ void pack_wsr(const float* __restrict__ w, float* __restrict__ wsr) {
    __shared__ float t[32][257];
    const int cout = blockIdx.x;
    const int tid = threadIdx.x;
    const float* wr = w + (size_t)cout * KSR + (size_t)tid * 64;
    float* wo = wsr + (size_t)cout * KSR;
#pragma unroll
    for (int half = 0; half < 2; half++) {
#pragma unroll
        for (int j4 = 0; j4 < 8; j4++) {
            float4 v = *(const float4*)(wr + half * 32 + j4 * 4);
            t[j4*4+0][tid] = v.x; t[j4*4+1][tid] = v.y;
            t[j4*4+2][tid] = v.z; t[j4*4+3][tid] = v.w;
        }
        __syncthreads();
#pragma unroll
        for (int j = 0; j < 32; j++)
            wo[(size_t)(half * 32 + j) * C_ + tid] = t[j][tid];
        __syncthreads();
    }
}

// ------------- 128x128 tf32 tensor-core GEMM -------------
// out[M,Nc] = (A+A2)[M,K] @ W[Nc,K]^T + bias ; Nc multiple of 128, M guarded.
// 256 threads = 8 warps (2 x 4); warp tile 64(M) x 32(N); mma m16n8k8 tf32.
__global__ void __launch_bounds__(256, 2)
gemm_tf32(const float* __restrict__ A, const float* __restrict__ A2,
          const float* __restrict__ W, const float* __restrict__ bias,
          float* __restrict__ out, int M, int K, int Nc) {
    __shared__ unsigned As[128][SPAD];
    __shared__ unsigned Ws[128][SPAD];
    const int tid = threadIdx.x;
    const int lane = tid & 31, warp = tid >> 5;
    const int wm = warp & 1, wn = warp >> 1;       // 2 x 4 warp grid
    const int qr = lane >> 2, qc = lane & 3;
    const int bm = blockIdx.y << 7, bn = blockIdx.x << 7;

    const int lr = tid >> 1;          // 0..127 staging row
    const int lc = (tid & 1) << 3;    // 0 or 8

    const int am = bm + lr;
    const bool aval = am < M;
    const float* Ap  = A + (size_t)am * K + lc;
    const float* A2p = A2 ? A2 + (size_t)am * K + lc : nullptr;
    const float* Wp  = W + (size_t)(bn + lr) * K + lc;

    float4 a0 = make_float4(0.f,0.f,0.f,0.f), a1 = a0, w0, w1;
    if (aval) {
        a0 = *(const float4*)(Ap);
        a1 = *(const float4*)(Ap + 4);
        if (A2p) {
            float4 b = *(const float4*)(A2p);
            a0.x += b.x; a0.y += b.y; a0.z += b.z; a0.w += b.w;
            b = *(const float4*)(A2p + 4);
            a1.x += b.x; a1.y += b.y; a1.z += b.z; a1.w += b.w;
        }
    }
    w0 = *(const float4*)(Wp);
    w1 = *(const float4*)(Wp + 4);

    float acc[4][4][4];
#pragma unroll
    for (int i = 0; i < 4; i++)
#pragma unroll
        for (int j = 0; j < 4; j++)
#pragma unroll
            for (int q = 0; q < 4; q++) acc[i][j][q] = 0.f;

    for (int k0 = 0; k0 < K; k0 += 16) {
        // stage (convert to tf32 once)
        uint4 ua = make_uint4(f2tf(a0.x), f2tf(a0.y), f2tf(a0.z), f2tf(a0.w));
        uint4 ub = make_uint4(f2tf(a1.x), f2tf(a1.y), f2tf(a1.z), f2tf(a1.w));
        *(uint4*)&As[lr][lc]     = ua;
        *(uint4*)&As[lr][lc + 4] = ub;
        ua = make_uint4(f2tf(w0.x), f2tf(w0.y), f2tf(w0.z), f2tf(w0.w));
        ub = make_uint4(f2tf(w1.x), f2tf(w1.y), f2tf(w1.z), f2tf(w1.w));
        *(uint4*)&Ws[lr][lc]     = ua;
        *(uint4*)&Ws[lr][lc + 4] = ub;
        __syncthreads();

        const int kn = k0 + 16;
        if (kn < K) {
            a0 = make_float4(0.f,0.f,0.f,0.f); a1 = a0;
            if (aval) {
                a0 = *(const float4*)(Ap + kn);
                a1 = *(const float4*)(Ap + kn + 4);
                if (A2p) {
                    float4 b = *(const float4*)(A2p + kn);
                    a0.x += b.x; a0.y += b.y; a0.z += b.z; a0.w += b.w;
                    b = *(const float4*)(A2p + kn + 4);
                    a1.x += b.x; a1.y += b.y; a1.z += b.z; a1.w += b.w;
                }
            }
            w0 = *(const float4*)(Wp + kn);
            w1 = *(const float4*)(Wp + kn + 4);
        }

#pragma unroll
        for (int kk = 0; kk < 16; kk += 8) {
            unsigned af[4][4], bf[4][2];
#pragma unroll
            for (int mt = 0; mt < 4; mt++) {
                int r0 = wm * 64 + mt * 16 + qr;
                af[mt][0] = As[r0][kk + qc];
                af[mt][1] = As[r0 + 8][kk + qc];
                af[mt][2] = As[r0][kk + 4 + qc];
                af[mt][3] = As[r0 + 8][kk + 4 + qc];
            }
#pragma unroll
            for (int nt = 0; nt < 4; nt++) {
                int nb = wn * 32 + nt * 8 + qr;
                bf[nt][0] = Ws[nb][kk + qc];
                bf[nt][1] = Ws[nb][kk + 4 + qc];
            }
#pragma unroll
            for (int mt = 0; mt < 4; mt++)
#pragma unroll
                for (int nt = 0; nt < 4; nt++)
                    mma8(acc[mt][nt], af[mt][0], af[mt][1], af[mt][2], af[mt][3],
                         bf[nt][0], bf[nt][1]);
        }
        __syncthreads();
    }

    // epilogue: c0,c1 at (qr, 2qc), c2,c3 at (qr+8, 2qc)
#pragma unroll
    for (int mt = 0; mt < 4; mt++) {
#pragma unroll
        for (int nt = 0; nt < 4; nt++) {
            int c = bn + wn * 32 + nt * 8 + qc * 2;
            float bb0 = bias ? bias[c] : 0.f;
            float bb1 = bias ? bias[c + 1] : 0.f;
            int r0 = bm + wm * 64 + mt * 16 + qr;
            if (r0 < M)
                *(float2*)(out + (size_t)r0 * Nc + c) =
                    make_float2(acc[mt][nt][0] + bb0, acc[mt][nt][1] + bb1);
            if (r0 + 8 < M)
                *(float2*)(out + (size_t)(r0 + 8) * Nc + c) =
                    make_float2(acc[mt][nt][2] + bb0, acc[mt][nt][3] + bb1);
        }
    }
}

// ---- SR conv split-K tf32 GEMM: one block-z per kernel position ----
__global__ void __launch_bounds__(256, 2)
srconv_tf32(const float* __restrict__ x, const float* __restrict__ wsr,
            float* __restrict__ part) {
    __shared__ unsigned As[128][SPAD];
    __shared__ unsigned Ws[128][SPAD];
    const int tid = threadIdx.x;
    const int lane = tid & 31, warp = tid >> 5;
    const int wm = warp & 1, wn = warp >> 1;
    const int qr = lane >> 2, qc = lane & 3;
    const int bn = blockIdx.x << 7;   // cout tile
    const int bm = blockIdx.y << 7;   // nr tile
    const int kz = blockIdx.z;        // kernel position 0..63
    const int kh = kz >> 4, kw = (kz >> 2) & 3, kd = kz & 3;

    const int lr = tid >> 1;
    const int lc = (tid & 1) << 3;

    const int nr = bm + lr;
    const bool aval = nr < NR;
    int tok = 0;
    if (aval) {
        int oh = nr / 49; int r = nr % 49; int ow = r / 7; int od = r % 7;
        tok = ((4 * oh + kh) * HDIM + 4 * ow + kw) * HDIM + 4 * od + kd;
    }
    const float* Ap = x + (size_t)tok * C_ + lc;
    const float* Wp = wsr + (size_t)(bn + lr) * KSR + (size_t)kz * C_ + lc;

    float4 a0 = make_float4(0.f,0.f,0.f,0.f), a1 = a0, w0, w1;
    if (aval) { a0 = *(const float4*)(Ap); a1 = *(const float4*)(Ap + 4); }
    w0 = *(const float4*)(Wp);
    w1 = *(const float4*)(Wp + 4);

    float acc[4][4][4];
#pragma unroll
    for (int i = 0; i < 4; i++)
#pragma unroll
        for (int j = 0; j < 4; j++)
#pragma unroll
            for (int q = 0; q < 4; q++) acc[i][j][q] = 0.f;

    for (int k0 = 0; k0 < C_; k0 += 16) {
        uint4 ua = make_uint4(f2tf(a0.x), f2tf(a0.y), f2tf(a0.z), f2tf(a0.w));
        uint4 ub = make_uint4(f2tf(a1.x), f2tf(a1.y), f2tf(a1.z), f2tf(a1.w));
        *(uint4*)&As[lr][lc]     = ua;
        *(uint4*)&As[lr][lc + 4] = ub;
        ua = make_uint4(f2tf(w0.x), f2tf(w0.y), f2tf(w0.z), f2tf(w0.w));
        ub = make_uint4(f2tf(w1.x), f2tf(w1.y), f2tf(w1.z), f2tf(w1.w));
        *(uint4*)&Ws[lr][lc]     = ua;
        *(uint4*)&Ws[lr][lc + 4] = ub;
        __syncthreads();

        const int kn = k0 + 16;
        if (kn < C_) {
            a0 = make_float4(0.f,0.f,0.f,0.f); a1 = a0;
            if (aval) { a0 = *(const float4*)(Ap + kn); a1 = *(const float4*)(Ap + kn + 4); }
            w0 = *(const float4*)(Wp + kn);
            w1 = *(const float4*)(Wp + kn + 4);
        }

#pragma unroll
        for (int kk = 0; kk < 16; kk += 8) {
            unsigned af[4][4], bf[4][2];
#pragma unroll
            for (int mt = 0; mt < 4; mt++) {
                int r0 = wm * 64 + mt * 16 + qr;
                af[mt][0] = As[r0][kk + qc];
                af[mt][1] = As[r0 + 8][kk + qc];
                af[mt][2] = As[r0][kk + 4 + qc];
                af[mt][3] = As[r0 + 8][kk + 4 + qc];
            }
#pragma unroll
            for (int nt = 0; nt < 4; nt++) {
                int nb = wn * 32 + nt * 8 + qr;
                bf[nt][0] = Ws[nb][kk + qc];
                bf[nt][1] = Ws[nb][kk + 4 + qc];
            }
#pragma unroll
            for (int mt = 0; mt < 4; mt++)
#pragma unroll
                for (int nt = 0; nt < 4; nt++)
                    mma8(acc[mt][nt], af[mt][0], af[mt][1], af[mt][2], af[mt][3],
                         bf[nt][0], bf[nt][1]);
        }
        __syncthreads();
    }

    float* pz = part + (size_t)kz * (NR * C_);
#pragma unroll
    for (int mt = 0; mt < 4; mt++) {
#pragma unroll
        for (int nt = 0; nt < 4; nt++) {
            int c = bn + wn * 32 + nt * 8 + qc * 2;
            int r0 = bm + wm * 64 + mt * 16 + qr;
            if (r0 < NR)
                *(float2*)(pz + (size_t)r0 * C_ + c) =
                    make_float2(acc[mt][nt][0], acc[mt][nt][1]);
            if (r0 + 8 < NR)
                *(float2*)(pz + (size_t)(r0 + 8) * C_ + c) =
                    make_float2(acc[mt][nt][2], acc[mt][nt][3]);
        }
    }
}

__global__ void sr_reduce(float* __restrict__ x1, const float* __restrict__ part) {
    int i4 = blockIdx.x * 256 + threadIdx.x;     // float4 index
    const int n4 = NR * C_ / 4;                  // 21952
    if (i4 < n4) {
        float4 s = make_float4(0.f, 0.f, 0.f, 0.f);
#pragma unroll
        for (int z = 0; z < KZ; z++) {
            float4 v = ((const float4*)part)[(size_t)z * n4 + i4];
            s.x += v.x; s.y += v.y; s.z += v.z; s.w += v.w;
        }
        ((float4*)x1)[i4] = s;
    }
}

// ---------------- depthwise 3x3x3 SAME conv; input = packed y (stride NP, off 512) ----
__global__ void dwconv3(const float* __restrict__ p, const float* __restrict__ w,
                        const float* __restrict__ b, float* __restrict__ out) {
    const int n = blockIdx.x;
    const int c = threadIdx.x;
    const int d  = n % HDIM;
    const int wv = (n / HDIM) % HDIM;
    const int h  = n / (HDIM * HDIM);

    float wreg[27];
#pragma unroll
    for (int j = 0; j < 27; j++) wreg[j] = w[c * 27 + j];

    float s = b[c];
#pragma unroll
    for (int kh = 0; kh < 3; kh++) {
        int hh = h + kh - 1;
        if (hh < 0 || hh >= HDIM) continue;
#pragma unroll
        for (int kw = 0; kw < 3; kw++) {
            int ww = wv + kw - 1;
            if (ww < 0 || ww >= HDIM) continue;
#pragma unroll
            for (int kd = 0; kd < 3; kd++) {
                int dd = d + kd - 1;
                if (dd < 0 || dd >= HDIM) continue;
                s += wreg[kh * 9 + kw * 3 + kd] *
                     p[(size_t)((hh * HDIM + ww) * HDIM + dd) * NP + 512 + c];
            }
        }
    }
    out[(size_t)n * C_ + c] = s;
}

// ---------------- layernorm (+sr bias) + exact GELU, in place ----------------
__global__ void ln_gelu(float* __restrict__ x1, const float* __restrict__ srb,
                        const float* __restrict__ g, const float* __restrict__ b) {
    __shared__ float red[256];
    const int r = blockIdx.x, c = threadIdx.x;
    float v = x1[(size_t)r * C_ + c] + srb[c];

    red[c] = v; __syncthreads();
    for (int s = 128; s > 0; s >>= 1) { if (c < s) red[c] += red[c + s]; __syncthreads(); }
    float mu = red[0] * (1.f / 256.f);
    __syncthreads();

    float dv = v - mu;
    red[c] = dv * dv; __syncthreads();
    for (int s = 128; s > 0; s >>= 1) { if (c < s) red[c] += red[c + s]; __syncthreads(); }
    float var = red[0] * (1.f / 256.f);

    float xn = dv * rsqrtf(var + 1e-5f) * g[c] + b[c];
    float out = 0.5f * xn * (1.f + erff(xn * 0.70710678118654752f));
    x1[(size_t)r * C_ + c] = out;
}

// ---------------- branch 1: global attention vs 343 reduced tokens ----------------
#define CH1 176
__global__ void attn_global(const float* __restrict__ p, const float* __restrict__ kv1,
                            float* __restrict__ o) {
    __shared__ float4 sk[CH1][8];
    __shared__ float4 sv[CH1][8];
    const int h = blockIdx.y;
    const int n = blockIdx.x * 256 + threadIdx.x;
    const bool valid = n < NTOK;

    float q[32];
    if (valid) {
        const float4* qp = (const float4*)(p + (size_t)n * NP + h * 32);
#pragma unroll
        for (int i = 0; i < 8; i++) {
            float4 t = qp[i];
            q[4*i] = t.x * SCALE_F; q[4*i+1] = t.y * SCALE_F;
            q[4*i+2] = t.z * SCALE_F; q[4*i+3] = t.w * SCALE_F;
        }
    }

    float l = 0.f, acc[32];
#pragma unroll
    for (int i = 0; i < 32; i++) acc[i] = 0.f;

    for (int c0 = 0; c0 < NR; c0 += CH1) {
        const int cn = min(CH1, NR - c0);
        for (int idx = threadIdx.x; idx < cn * 8; idx += 256) {
            int m = idx >> 3, dq = idx & 7;
            sk[m][dq] = *(const float4*)(kv1 + (size_t)(c0 + m) * C_ + h * 32 + dq * 4);
            sv[m][dq] = *(const float4*)(kv1 + (size_t)(c0 + m) * C_ + 128 + h * 32 + dq * 4);
        }
        __syncthreads();
        if (valid) {
            for (int m = 0; m < cn; m++) {
                float s = 0.f;
#pragma unroll
                for (int i = 0; i < 8; i++) {
                    float4 kk = sk[m][i];
                    s += q[4*i] * kk.x + q[4*i+1] * kk.y
                       + q[4*i+2] * kk.z + q[4*i+3] * kk.w;
                }
                float pw = __expf(s);
                l += pw;
#pragma unroll
                for (int i = 0; i < 8; i++) {
                    float4 vv = sv[m][i];
                    acc[4*i]   += pw * vv.x;
                    acc[4*i+1] += pw * vv.y;
                    acc[4*i+2] += pw * vv.z;
                    acc[4*i+3] += pw * vv.w;
                }
            }
        }
        __syncthreads();
    }

    if (valid) {
        float inv = 1.f / l;
        float4* op = (float4*)(o + (size_t)n * C_ + h * 32);
#pragma unroll
        for (int i = 0; i < 8; i++)
            op[i] = make_float4(acc[4*i]*inv, acc[4*i+1]*inv,
                                acc[4*i+2]*inv, acc[4*i+3]*inv);
    }
}

// ---------------- branch 2: 7x7x7 windowed attention (packed q/kv) ----------------
__global__ void attn_window(const float* __restrict__ p, float* __restrict__ o) {
    __shared__ float4 sk[CH1][8];
    __shared__ float4 sv[CH1][8];
    const int h = blockIdx.y;
    const int w = blockIdx.x;                 // 0..63
    const int wh = w >> 4, ww = (w >> 2) & 3, wd = w & 3;
    const int t = threadIdx.x;
    const bool valid = t < NR;

    int n = 0;
    if (valid) {
        int ih = t / 49, r = t % 49, iw = r / 7, id = r % 7;
        n = ((wh * 7 + ih) * HDIM + ww * 7 + iw) * HDIM + wd * 7 + id;
    }

    float q[32];
    if (valid) {
        const float4* qp = (const float4*)(p + (size_t)n * NP + 128 + h * 32);
#pragma unroll
        for (int i = 0; i < 8; i++) {
            float4 tt = qp[i];
            q[4*i] = tt.x * SCALE_F; q[4*i+1] = tt.y * SCALE_F;
            q[4*i+2] = tt.z * SCALE_F; q[4*i+3] = tt.w * SCALE_F;
        }
    }

    float l = 0.f, acc[32];
#pragma unroll
    for (int i = 0; i < 32; i++) acc[i] = 0.f;

    for (int c0 = 0; c0 < NR; c0 += CH1) {
        const int cn = min(CH1, NR - c0);
        for (int idx = t; idx < cn * 8; idx += 352) {
            int m = idx >> 3, dq = idx & 7;
            int tm = c0 + m;
            int ih = tm / 49, r = tm % 49, iw = r / 7, id = r % 7;
            int nm = ((wh * 7 + ih) * HDIM + ww * 7 + iw) * HDIM + wd * 7 + id;
            sk[m][dq] = *(const float4*)(p + (size_t)nm * NP + 256 + h * 32 + dq * 4);
            sv[m][dq] = *(const float4*)(p + (size_t)nm * NP + 384 + h * 32 + dq * 4);
        }
        __syncthreads();
        if (valid) {
            for (int m = 0; m < cn; m++) {
                float s = 0.f;
#pragma unroll
                for (int i = 0; i < 8; i++) {
                    float4 kk = sk[m][i];
                    s += q[4*i] * kk.x + q[4*i+1] * kk.y
                       + q[4*i+2] * kk.z + q[4*i+3] * kk.w;
                }
                float pw = __expf(s);
                l += pw;
#pragma unroll
                for (int i = 0; i < 8; i++) {
                    float4 vv = sv[m][i];
                    acc[4*i]   += pw * vv.x;
                    acc[4*i+1] += pw * vv.y;
                    acc[4*i+2] += pw * vv.z;
                    acc[4*i+3] += pw * vv.w;
                }
            }
        }
        __syncthreads();
    }

    if (valid) {
        float inv = 1.f / l;
        float4* op = (float4*)(o + (size_t)n * C_ + 128 + h * 32);
#pragma unroll
        for (int i = 0; i < 8; i++)
            op[i] = make_float4(acc[4*i]*inv, acc[4*i+1]*inv,
                                acc[4*i+2]*inv, acc[4*i+3]*inv);
    }
}

// ---------------- launch ----------------
extern "C" void kernel_launch(void* const* d_in, const int* in_sizes, int n_in,
                              void* d_out, int out_size) {
    const float* x       = (const float*)d_in[0];
    const float* lepe_w  = (const float*)d_in[4];
    const float* lepe_b  = (const float*)d_in[5];
    const float* lepe_cw = (const float*)d_in[6];
    const float* lepe_cb = (const float*)d_in[7];
    const float* sr_w    = (const float*)d_in[8];
    const float* sr_b    = (const float*)d_in[9];
    const float* norm_g  = (const float*)d_in[10];
    const float* norm_b  = (const float*)d_in[11];
    const float* q1_w    = (const float*)d_in[12];
    const float* kv1_w   = (const float*)d_in[13];
    const float* q2_w    = (const float*)d_in[14];
    const float* kv2_w   = (const float*)d_in[15];
    const float* proj_w  = (const float*)d_in[16];
    const float* proj_b  = (const float*)d_in[17];
    float* out = (float*)d_out;

    float *p, *lepe, *x1p, *x1, *kv1, *o, *wp, *bp, *wsr;
    cudaGetSymbolAddress((void**)&p,    g_p);
    cudaGetSymbolAddress((void**)&lepe, g_lepe);
    cudaGetSymbolAddress((void**)&x1p,  g_x1p);
    cudaGetSymbolAddress((void**)&x1,   g_x1);
    cudaGetSymbolAddress((void**)&kv1,  g_kv1);
    cudaGetSymbolAddress((void**)&o,    g_o);
    cudaGetSymbolAddress((void**)&wp,   g_wp);
    cudaGetSymbolAddress((void**)&bp,   g_bp);
    cudaGetSymbolAddress((void**)&wsr,  g_wsr);

    const int MT = (NTOK + 127) / 128;   // 172 row tiles

    // Pack projection weights, then one fused tf32 GEMM: [q1|q2|kv2|y] = x @ Wp^T + bp
    pack_w<<<(NP * C_ + 255) / 256, 256>>>(q1_w, q2_w, kv2_w, lepe_w, lepe_b, wp, bp);
    gemm_tf32<<<dim3(NP / 128, MT), 256>>>(x, nullptr, wp, bp, p, NTOK, C_, NP);

    // LePE depthwise conv from packed y
    dwconv3<<<NTOK, C_>>>(p, lepe_cw, lepe_cb, lepe);

    // SR conv: transpose weights, 64-way split-K tf32 GEMM, reduce, LN+GELU, kv1
    pack_wsr<<<C_, 256>>>(sr_w, wsr);
    srconv_tf32<<<dim3(C_ / 128, (NR + 127) / 128, KZ), 256>>>(x, wsr, x1p);
    sr_reduce<<<(NR * C_ / 4 + 255) / 256, 256>>>(x1, x1p);
    ln_gelu<<<NR, C_>>>(x1, sr_b, norm_g, norm_b);
    gemm_tf32<<<dim3(C_ / 128, (NR + 127) / 128), 256>>>(x1, nullptr, kv1_w, nullptr, kv1, NR, C_, C_);

    // Attention branches -> g_o (cols 0..127 branch1, 128..255 branch2)
    attn_global<<<dim3((NTOK + 255) / 256, H2_), 256>>>(p, kv1, o);
    attn_window<<<dim3(64, H2_), 352>>>(p, o);

    // Final projection with fused (+lepe)
    gemm_tf32<<<dim3(C_ / 128, MT), 256>>>(o, lepe, proj_w, proj_b, out, NTOK, C_, C_);
}